// round 12
// baseline (speedup 1.0000x reference)
#include <cuda_runtime.h>
#include <cuda_fp16.h>
#include <cstdint>

// ---------------------------------------------------------------- shapes
#define BB   4
#define SS   2048
#define DIN  4096
#define DOUT 4096
#define CAP  1024
#define MTOT (BB * SS)       // 8192

// GEMM tiling
#define BM 128
#define BN 256
#define BK 32                 // fp16 elems per stage chunk
#define NCHUNK (DIN / BK)     // 128
#define STAGES 5
#define NTHREADS 512

// smem geometry: rows padded 32 -> 40 halves (80B pitch, conflict-free ldmatrix)
#define ROWP 40
#define A_BUF_B (BM * ROWP * 2)     // 10240
#define B_BUF_B (BN * ROWP * 2)     // 20480
#define STAGE_B (A_BUF_B + B_BUF_B)           // 30720
#define SM_STAGE0 2048
#define GEMM_SMEM (SM_STAGE0 + STAGES * STAGE_B)   // 155648

// ---------------------------------------------------------------- scratch
__device__ float g_scores[CAP];
__device__ float g_mem_out[DOUT];
__device__ __align__(1024) __half g_xh[(size_t)MTOT * DIN];
__device__ __align__(1024) __half g_wh[(size_t)DOUT * DIN];

// ---------------------------------------------------------------- PTX helpers
__device__ __forceinline__ uint32_t smem_to_u32(const void* p) {
    uint32_t a;
    asm("{ .reg .u64 t; cvta.to.shared.u64 t, %1; cvt.u32.u64 %0, t; }" : "=r"(a) : "l"(p));
    return a;
}
__device__ __forceinline__ void cp16(uint32_t dst, const void* src) {
    asm volatile("cp.async.cg.shared.global [%0], [%1], 16;" :: "r"(dst), "l"(src));
}
#define CP_COMMIT() asm volatile("cp.async.commit_group;" ::: "memory")
#define CP_WAIT(n)  asm volatile("cp.async.wait_group %0;" :: "n"(n) : "memory")

__device__ __forceinline__ void ldsm_x4(uint32_t* r, uint32_t addr) {
    asm volatile("ldmatrix.sync.aligned.m8n8.x4.shared.b16 {%0,%1,%2,%3}, [%4];"
        : "=r"(r[0]), "=r"(r[1]), "=r"(r[2]), "=r"(r[3]) : "r"(addr));
}
__device__ __forceinline__ void mma16816(float* c, const uint32_t* a, const uint32_t* b) {
    asm volatile("mma.sync.aligned.m16n8k16.row.col.f32.f16.f16.f32 "
        "{%0,%1,%2,%3}, {%4,%5,%6,%7}, {%8,%9}, {%0,%1,%2,%3};"
        : "+f"(c[0]), "+f"(c[1]), "+f"(c[2]), "+f"(c[3])
        : "r"(a[0]), "r"(a[1]), "r"(a[2]), "r"(a[3]), "r"(b[0]), "r"(b[1]));
}

// ---------------------------------------------------------------- small kernels
__global__ void scores_kernel(const float* __restrict__ keys, const float* __restrict__ x) {
    const int c = blockIdx.x;
    const float4* row = reinterpret_cast<const float4*>(keys + (size_t)c * DIN);
    const float4* q   = reinterpret_cast<const float4*>(x);
    float sum = 0.f;
    for (int i = threadIdx.x; i < DIN / 4; i += 256) {
        float4 a = row[i], b = q[i];
        sum += a.x * b.x + a.y * b.y + a.z * b.z + a.w * b.w;
    }
    #pragma unroll
    for (int off = 16; off; off >>= 1) sum += __shfl_down_sync(0xffffffffu, sum, off);
    __shared__ float red[8];
    if ((threadIdx.x & 31) == 0) red[threadIdx.x >> 5] = sum;
    __syncthreads();
    if (threadIdx.x < 8) {
        float v = red[threadIdx.x];
        #pragma unroll
        for (int off = 4; off; off >>= 1) v += __shfl_down_sync(0xffu, v, off);
        if (threadIdx.x == 0) g_scores[c] = v;
    }
}

// fused softmax + memout: each block recomputes softmax (cheap) and fills 256 outputs
__global__ void memout_fused_kernel(const float* __restrict__ vals) {
    __shared__ float s_attn[CAP];
    __shared__ float red[8];
    const int t = threadIdx.x;   // 256 threads
    // local max over this thread's 4 scores
    float v[4], m = -1e30f;
    #pragma unroll
    for (int j = 0; j < 4; j++) { v[j] = g_scores[t * 4 + j]; m = fmaxf(m, v[j]); }
    #pragma unroll
    for (int off = 16; off; off >>= 1) m = fmaxf(m, __shfl_xor_sync(0xffffffffu, m, off));
    if ((t & 31) == 0) red[t >> 5] = m;
    __syncthreads();
    if (t < 8) {
        float w = red[t];
        #pragma unroll
        for (int off = 4; off; off >>= 1) w = fmaxf(w, __shfl_xor_sync(0xffu, w, off));
        red[t] = w;
    }
    __syncthreads();
    m = fmaxf(fmaxf(red[0], red[1]), fmaxf(red[2], red[3]));
    m = fmaxf(m, fmaxf(fmaxf(red[4], red[5]), fmaxf(red[6], red[7])));
    __syncthreads();
    float s = 0.f;
    #pragma unroll
    for (int j = 0; j < 4; j++) { v[j] = expf(v[j] - m); s += v[j]; }
    #pragma unroll
    for (int off = 16; off; off >>= 1) s += __shfl_xor_sync(0xffffffffu, s, off);
    if ((t & 31) == 0) red[t >> 5] = s;
    __syncthreads();
    if (t < 8) {
        float w = red[t];
        #pragma unroll
        for (int off = 4; off; off >>= 1) w += __shfl_xor_sync(0xffu, w, off);
        red[t] = w;
    }
    __syncthreads();
    s = red[0] + red[1] + red[2] + red[3] + red[4] + red[5] + red[6] + red[7];
    const float inv = 1.f / s;
    #pragma unroll
    for (int j = 0; j < 4; j++) s_attn[t * 4 + j] = v[j] * inv;
    __syncthreads();

    const int o = blockIdx.x * 256 + t;
    float acc = 0.f;
    #pragma unroll 4
    for (int c = 0; c < CAP; c++) acc = fmaf(s_attn[c], vals[(size_t)c * DOUT + o], acc);
    g_mem_out[o] = acc;
}

// fp32 -> fp16 cast (8 elems/thread)
__global__ void convert_single_kernel(const float* __restrict__ src,
                                      __half* __restrict__ dst, int n8) {
    int i = blockIdx.x * blockDim.x + threadIdx.x;
    if (i >= n8) return;
    float4 v0 = reinterpret_cast<const float4*>(src)[i * 2 + 0];
    float4 v1 = reinterpret_cast<const float4*>(src)[i * 2 + 1];
    __half2 h[4];
    h[0].x = __float2half_rn(v0.x); h[0].y = __float2half_rn(v0.y);
    h[1].x = __float2half_rn(v0.z); h[1].y = __float2half_rn(v0.w);
    h[2].x = __float2half_rn(v1.x); h[2].y = __float2half_rn(v1.y);
    h[3].x = __float2half_rn(v1.z); h[3].y = __float2half_rn(v1.w);
    reinterpret_cast<uint4*>(dst)[i] = *reinterpret_cast<uint4*>(h);
}

// ---------------------------------------------------------------- main GEMM
// C[m,n] = scale[n] * (xh[m,:].wh[n,:]) + 0.01*mem_out[n]
// 512 threads, warp layout 2(m) x 8(n); warp tile 64m x 32n. 4 warps/SMSP.
__global__ __launch_bounds__(NTHREADS, 1)
void gemm_mma_kernel(const float* __restrict__ scales, float* __restrict__ C) {
    extern __shared__ char smem[];
    const uint32_t smem_u32 = smem_to_u32(smem);
    float* s_scale = reinterpret_cast<float*>(smem);
    float* s_memo  = reinterpret_cast<float*>(smem + 1024);

    const int tid  = threadIdx.x;
    const int wid  = tid >> 5;
    const int lane = tid & 31;
    const int warp_m = wid & 1;        // 2 strips of 64 rows
    const int warp_n = wid >> 1;       // 8 strips of 32 cols
    const int block_m = blockIdx.x * BM;   // m fast -> consecutive CTAs share W tile
    const int block_n = blockIdx.y * BN;

    // epilogue vectors
    for (int i = tid; i < BN; i += NTHREADS) {
        s_scale[i] = scales[block_n + i];
        s_memo[i]  = 0.01f * g_mem_out[block_n + i];
    }

    const __half* gXh = g_xh + (size_t)block_m * DIN;
    const __half* gWh = g_wh + (size_t)block_n * DIN;

    // A: 512x16B = exactly 1 per thread; B: 1024x16B = 2 per thread
    auto load_stage = [&](int kt, int s) {
        const int k0 = kt * BK;
        const uint32_t st = smem_u32 + SM_STAGE0 + s * STAGE_B;
        const uint32_t sA = st;
        const uint32_t sB = st + A_BUF_B;
        {
            int row = tid >> 2, c = tid & 3;
            size_t go = (size_t)row * DIN + k0 + c * 8;
            uint32_t so = row * (ROWP * 2) + c * 16;
            cp16(sA + so, gXh + go);
        }
        #pragma unroll
        for (int j = 0; j < 2; j++) {
            int idx = tid + NTHREADS * j;
            int row = idx >> 2, c = idx & 3;
            size_t go = (size_t)row * DIN + k0 + c * 8;
            uint32_t so = row * (ROWP * 2) + c * 16;
            cp16(sB + so, gWh + go);
        }
        CP_COMMIT();
    };

    float acc[4][4][4];
    #pragma unroll
    for (int i = 0; i < 4; i++)
        #pragma unroll
        for (int t = 0; t < 4; t++)
            #pragma unroll
            for (int r = 0; r < 4; r++) acc[i][t][r] = 0.f;

    // ldmatrix lane address components
    const int a_row = lane & 15;
    const int a_k   = (lane >> 4) * 8;
    const int b_row = (lane & 7) + ((lane >> 4) << 3);
    const int b_k   = ((lane >> 3) & 1) * 8;

    // fragments: 4 A frags (64 rows) + 2 B frags (32 cols) per kk step
    auto ldfrags = [&](uint32_t st, int kk, uint32_t af[4][4], uint32_t bf[2][4]) {
        const uint32_t sA = st;
        const uint32_t sB = st + A_BUF_B;
        #pragma unroll
        for (int i = 0; i < 4; i++) {
            uint32_t off = (uint32_t)(warp_m * 64 + i * 16 + a_row) * (ROWP * 2)
                         + (kk + a_k) * 2;
            ldsm_x4(af[i], sA + off);
        }
        #pragma unroll
        for (int p = 0; p < 2; p++) {
            uint32_t off = (uint32_t)(warp_n * 32 + p * 16 + b_row) * (ROWP * 2)
                         + (kk + b_k) * 2;
            ldsm_x4(bf[p], sB + off);
        }
    };

    auto do_mma = [&](uint32_t af[4][4], uint32_t bf[2][4]) {
        #pragma unroll
        for (int p = 0; p < 2; p++) {
            #pragma unroll
            for (int i = 0; i < 4; i++) {
                mma16816(acc[i][2 * p],     af[i], bf[p]);
                mma16816(acc[i][2 * p + 1], af[i], bf[p] + 2);
            }
        }
    };

    // prologue: fill 4 of 5 stages
    load_stage(0, 0);
    load_stage(1, 1);
    load_stage(2, 2);
    load_stage(3, 3);
    CP_WAIT(2);            // stages 0 and 1 resident
    __syncthreads();

    uint32_t afA[4][4], bfA[2][4], afB[4][4], bfB[2][4];
    ldfrags(smem_u32 + SM_STAGE0, 0, afA, bfA);

    for (int kt = 0; kt < NCHUNK; kt++) {
        const uint32_t stc = smem_u32 + SM_STAGE0 + (kt % STAGES) * STAGE_B;
        if (kt + 4 < NCHUNK) load_stage(kt + 4, (kt + 4) % STAGES);

        // half 0: prefetch kk=16 frags, mma on kk=0 frags
        ldfrags(stc, 16, afB, bfB);
        do_mma(afA, bfA);

        // half 1: prefetch next stage kk=0 frags (stage kt+1 resident), mma kk=16
        if (kt + 1 < NCHUNK) {
            const uint32_t stn = smem_u32 + SM_STAGE0 + ((kt + 1) % STAGES) * STAGE_B;
            ldfrags(stn, 0, afA, bfA);
        }
        do_mma(afB, bfB);

        // invariant for kt+1: stages kt+1, kt+2 resident
        if (kt + 1 < NCHUNK) {
            CP_WAIT(2);
            __syncthreads();
        }
    }

    // ---------------- epilogue ----------------
    const int groupID = lane >> 2;
    const int tidg    = lane & 3;
    #pragma unroll
    for (int i = 0; i < 4; i++) {
        const int m0 = block_m + warp_m * 64 + i * 16 + groupID;
        #pragma unroll
        for (int t = 0; t < 4; t++) {
            const int ln = warp_n * 32 + t * 8 + tidg * 2;
            const float sc0 = s_scale[ln],     mo0 = s_memo[ln];
            const float sc1 = s_scale[ln + 1], mo1 = s_memo[ln + 1];
            float2 o0, o1;
            o0.x = fmaf(acc[i][t][0], sc0, mo0);
            o0.y = fmaf(acc[i][t][1], sc1, mo1);
            o1.x = fmaf(acc[i][t][2], sc0, mo0);
            o1.y = fmaf(acc[i][t][3], sc1, mo1);
            *reinterpret_cast<float2*>(C + (size_t)m0 * DOUT + block_n + ln)       = o0;
            *reinterpret_cast<float2*>(C + (size_t)(m0 + 8) * DOUT + block_n + ln) = o1;
        }
    }
}

// ---------------------------------------------------------------- host launch
extern "C" void kernel_launch(void* const* d_in, const int* in_sizes, int n_in,
                              void* d_out, int out_size) {
    const float* x      = (const float*)d_in[0];  // [B,S,DIN]
    const float* wlat   = (const float*)d_in[1];  // [DOUT,DIN]
    const float* wscale = (const float*)d_in[2];  // [DOUT,1]
    const float* mkeys  = (const float*)d_in[3];  // [CAP,DIN]
    const float* mvals  = (const float*)d_in[4];  // [CAP,DOUT]
    float* out = (float*)d_out;                   // [B,S,DOUT]
    (void)in_sizes; (void)n_in; (void)out_size;

    void *p_xh, *p_wh;
    cudaGetSymbolAddress(&p_xh, g_xh);
    cudaGetSymbolAddress(&p_wh, g_wh);

    // conversions (8 elems/thread)
    {
        int n8 = MTOT * DIN / 8;
        convert_single_kernel<<<n8 / 256, 256>>>(x, (__half*)p_xh, n8);
        int w8 = DOUT * DIN / 8;
        convert_single_kernel<<<w8 / 256, 256>>>(wlat, (__half*)p_wh, w8);
    }

    // associative memory path
    scores_kernel<<<CAP, 256>>>(mkeys, x);
    memout_fused_kernel<<<DOUT / 256, 256>>>(mvals);

    // main GEMM
    cudaFuncSetAttribute(gemm_mma_kernel, cudaFuncAttributeMaxDynamicSharedMemorySize, GEMM_SMEM);
    dim3 grid(MTOT / BM, DOUT / BN);   // 64 x 16 (m fast)
    gemm_mma_kernel<<<grid, NTHREADS, GEMM_SMEM>>>(wscale, out);
}

// round 13
// speedup vs baseline: 1.1516x; 1.1516x over previous
#include <cuda_runtime.h>
#include <cuda_fp16.h>
#include <cstdint>

// ---------------------------------------------------------------- shapes
#define BB   4
#define SS   2048
#define DIN  4096
#define DOUT 4096
#define CAP  1024
#define MTOT (BB * SS)       // 8192

// GEMM tiling
#define BM 128
#define BN 256
#define BK 32                 // fp16 elems per stage chunk
#define NCHUNK (DIN / BK)     // 128
#define STAGES 5
#define NTHREADS 512

// smem geometry: rows padded 32 -> 40 halves (80B pitch, conflict-free ldmatrix)
#define ROWP 40
#define A_BUF_B (BM * ROWP * 2)     // 10240
#define B_BUF_B (BN * ROWP * 2)     // 20480
#define STAGE_B (A_BUF_B + B_BUF_B)           // 30720
#define SM_STAGE0 2048
#define GEMM_SMEM (SM_STAGE0 + STAGES * STAGE_B)   // 155648

// ---------------------------------------------------------------- scratch
__device__ float g_scores[CAP];
__device__ float g_mem_out[DOUT];
__device__ __align__(1024) __half g_xh[(size_t)MTOT * DIN];
__device__ __align__(1024) __half g_wh[(size_t)DOUT * DIN];

// ---------------------------------------------------------------- PTX helpers
__device__ __forceinline__ uint32_t smem_to_u32(const void* p) {
    uint32_t a;
    asm("{ .reg .u64 t; cvta.to.shared.u64 t, %1; cvt.u32.u64 %0, t; }" : "=r"(a) : "l"(p));
    return a;
}
__device__ __forceinline__ void cp16(uint32_t dst, const void* src) {
    asm volatile("cp.async.cg.shared.global [%0], [%1], 16;" :: "r"(dst), "l"(src));
}
#define CP_COMMIT() asm volatile("cp.async.commit_group;" ::: "memory")
#define CP_WAIT(n)  asm volatile("cp.async.wait_group %0;" :: "n"(n) : "memory")

__device__ __forceinline__ void ldsm_x4(uint32_t* r, uint32_t addr) {
    asm volatile("ldmatrix.sync.aligned.m8n8.x4.shared.b16 {%0,%1,%2,%3}, [%4];"
        : "=r"(r[0]), "=r"(r[1]), "=r"(r[2]), "=r"(r[3]) : "r"(addr));
}
__device__ __forceinline__ void mma16816(float* c, const uint32_t* a, const uint32_t* b) {
    asm volatile("mma.sync.aligned.m16n8k16.row.col.f32.f16.f16.f32 "
        "{%0,%1,%2,%3}, {%4,%5,%6,%7}, {%8,%9}, {%0,%1,%2,%3};"
        : "+f"(c[0]), "+f"(c[1]), "+f"(c[2]), "+f"(c[3])
        : "r"(a[0]), "r"(a[1]), "r"(a[2]), "r"(a[3]), "r"(b[0]), "r"(b[1]));
}

// ---------------------------------------------------------------- small kernels
__global__ void scores_kernel(const float* __restrict__ keys, const float* __restrict__ x) {
    const int c = blockIdx.x;
    const float4* row = reinterpret_cast<const float4*>(keys + (size_t)c * DIN);
    const float4* q   = reinterpret_cast<const float4*>(x);
    float sum = 0.f;
    for (int i = threadIdx.x; i < DIN / 4; i += 256) {
        float4 a = row[i], b = q[i];
        sum += a.x * b.x + a.y * b.y + a.z * b.z + a.w * b.w;
    }
    #pragma unroll
    for (int off = 16; off; off >>= 1) sum += __shfl_down_sync(0xffffffffu, sum, off);
    __shared__ float red[8];
    if ((threadIdx.x & 31) == 0) red[threadIdx.x >> 5] = sum;
    __syncthreads();
    if (threadIdx.x < 8) {
        float v = red[threadIdx.x];
        #pragma unroll
        for (int off = 4; off; off >>= 1) v += __shfl_down_sync(0xffu, v, off);
        if (threadIdx.x == 0) g_scores[c] = v;
    }
}

// fused softmax + memout. grid=128 blocks, 256 threads.
// Each block: recompute 1024-wide softmax from g_scores (cheap), then compute
// 32 outputs; 8 threads per output, each covering 128 K-steps (coalesced loads).
__global__ void memout_fused_kernel(const float* __restrict__ vals) {
    __shared__ float s_attn[CAP];
    __shared__ float red[8];
    __shared__ float s_part[8][32];
    const int t = threadIdx.x;
    const int lane = t & 31;
    const int wrp  = t >> 5;

    // ---- softmax (threads handle 4 scores each) ----
    float v[4], m = -1e30f;
    #pragma unroll
    for (int j = 0; j < 4; j++) { v[j] = g_scores[t * 4 + j]; m = fmaxf(m, v[j]); }
    #pragma unroll
    for (int off = 16; off; off >>= 1) m = fmaxf(m, __shfl_xor_sync(0xffffffffu, m, off));
    if (lane == 0) red[wrp] = m;
    __syncthreads();
    if (t < 8) {
        float w = red[t];
        #pragma unroll
        for (int off = 4; off; off >>= 1) w = fmaxf(w, __shfl_xor_sync(0xffu, w, off));
        red[t] = w;
    }
    __syncthreads();
    m = red[0];
    __syncthreads();               // red reused below
    float s = 0.f;
    #pragma unroll
    for (int j = 0; j < 4; j++) { v[j] = expf(v[j] - m); s += v[j]; }
    #pragma unroll
    for (int off = 16; off; off >>= 1) s += __shfl_xor_sync(0xffffffffu, s, off);
    if (lane == 0) red[wrp] = s;
    __syncthreads();
    if (t < 8) {
        float w = red[t];
        #pragma unroll
        for (int off = 4; off; off >>= 1) w += __shfl_xor_sync(0xffu, w, off);
        red[t] = w;
    }
    __syncthreads();
    const float inv = 1.f / red[0];   // total sum (fix: take red[0], do NOT re-sum)
    #pragma unroll
    for (int j = 0; j < 4; j++) s_attn[t * 4 + j] = v[j] * inv;
    __syncthreads();

    // ---- memout: 32 outputs per block, 8 segments of 128 c's per output ----
    const int o   = blockIdx.x * 32 + (t & 31);
    const int seg = t >> 5;           // 0..7
    const int c0  = seg * 128;
    float acc = 0.f;
    #pragma unroll 4
    for (int c = 0; c < 128; c++)
        acc = fmaf(s_attn[c0 + c], vals[(size_t)(c0 + c) * DOUT + o], acc);
    s_part[seg][t & 31] = acc;
    __syncthreads();
    if (t < 32) {
        float tot = 0.f;
        #pragma unroll
        for (int g = 0; g < 8; g++) tot += s_part[g][t];
        g_mem_out[blockIdx.x * 32 + t] = tot;
    }
}

// fp32 -> fp16 cast (8 elems/thread)
__global__ void convert_single_kernel(const float* __restrict__ src,
                                      __half* __restrict__ dst, int n8) {
    int i = blockIdx.x * blockDim.x + threadIdx.x;
    if (i >= n8) return;
    float4 v0 = reinterpret_cast<const float4*>(src)[i * 2 + 0];
    float4 v1 = reinterpret_cast<const float4*>(src)[i * 2 + 1];
    __half2 h[4];
    h[0].x = __float2half_rn(v0.x); h[0].y = __float2half_rn(v0.y);
    h[1].x = __float2half_rn(v0.z); h[1].y = __float2half_rn(v0.w);
    h[2].x = __float2half_rn(v1.x); h[2].y = __float2half_rn(v1.y);
    h[3].x = __float2half_rn(v1.z); h[3].y = __float2half_rn(v1.w);
    reinterpret_cast<uint4*>(dst)[i] = *reinterpret_cast<uint4*>(h);
}

// ---------------------------------------------------------------- main GEMM
// C[m,n] = scale[n] * (xh[m,:].wh[n,:]) + 0.01*mem_out[n]
// 512 threads, warp layout 2(m) x 8(n); warp tile 64m x 32n. (unchanged from R12)
__global__ __launch_bounds__(NTHREADS, 1)
void gemm_mma_kernel(const float* __restrict__ scales, float* __restrict__ C) {
    extern __shared__ char smem[];
    const uint32_t smem_u32 = smem_to_u32(smem);
    float* s_scale = reinterpret_cast<float*>(smem);
    float* s_memo  = reinterpret_cast<float*>(smem + 1024);

    const int tid  = threadIdx.x;
    const int wid  = tid >> 5;
    const int lane = tid & 31;
    const int warp_m = wid & 1;        // 2 strips of 64 rows
    const int warp_n = wid >> 1;       // 8 strips of 32 cols
    const int block_m = blockIdx.x * BM;   // m fast -> consecutive CTAs share W tile
    const int block_n = blockIdx.y * BN;

    // epilogue vectors
    for (int i = tid; i < BN; i += NTHREADS) {
        s_scale[i] = scales[block_n + i];
        s_memo[i]  = 0.01f * g_mem_out[block_n + i];
    }

    const __half* gXh = g_xh + (size_t)block_m * DIN;
    const __half* gWh = g_wh + (size_t)block_n * DIN;

    // A: 512x16B = exactly 1 per thread; B: 1024x16B = 2 per thread
    auto load_stage = [&](int kt, int s) {
        const int k0 = kt * BK;
        const uint32_t st = smem_u32 + SM_STAGE0 + s * STAGE_B;
        const uint32_t sA = st;
        const uint32_t sB = st + A_BUF_B;
        {
            int row = tid >> 2, c = tid & 3;
            size_t go = (size_t)row * DIN + k0 + c * 8;
            uint32_t so = row * (ROWP * 2) + c * 16;
            cp16(sA + so, gXh + go);
        }
        #pragma unroll
        for (int j = 0; j < 2; j++) {
            int idx = tid + NTHREADS * j;
            int row = idx >> 2, c = idx & 3;
            size_t go = (size_t)row * DIN + k0 + c * 8;
            uint32_t so = row * (ROWP * 2) + c * 16;
            cp16(sB + so, gWh + go);
        }
        CP_COMMIT();
    };

    float acc[4][4][4];
    #pragma unroll
    for (int i = 0; i < 4; i++)
        #pragma unroll
        for (int t = 0; t < 4; t++)
            #pragma unroll
            for (int r = 0; r < 4; r++) acc[i][t][r] = 0.f;

    // ldmatrix lane address components
    const int a_row = lane & 15;
    const int a_k   = (lane >> 4) * 8;
    const int b_row = (lane & 7) + ((lane >> 4) << 3);
    const int b_k   = ((lane >> 3) & 1) * 8;

    // fragments: 4 A frags (64 rows) + 2 B frags (32 cols) per kk step
    auto ldfrags = [&](uint32_t st, int kk, uint32_t af[4][4], uint32_t bf[2][4]) {
        const uint32_t sA = st;
        const uint32_t sB = st + A_BUF_B;
        #pragma unroll
        for (int i = 0; i < 4; i++) {
            uint32_t off = (uint32_t)(warp_m * 64 + i * 16 + a_row) * (ROWP * 2)
                         + (kk + a_k) * 2;
            ldsm_x4(af[i], sA + off);
        }
        #pragma unroll
        for (int p = 0; p < 2; p++) {
            uint32_t off = (uint32_t)(warp_n * 32 + p * 16 + b_row) * (ROWP * 2)
                         + (kk + b_k) * 2;
            ldsm_x4(bf[p], sB + off);
        }
    };

    auto do_mma = [&](uint32_t af[4][4], uint32_t bf[2][4]) {
        #pragma unroll
        for (int p = 0; p < 2; p++) {
            #pragma unroll
            for (int i = 0; i < 4; i++) {
                mma16816(acc[i][2 * p],     af[i], bf[p]);
                mma16816(acc[i][2 * p + 1], af[i], bf[p] + 2);
            }
        }
    };

    // prologue: fill 4 of 5 stages
    load_stage(0, 0);
    load_stage(1, 1);
    load_stage(2, 2);
    load_stage(3, 3);
    CP_WAIT(2);            // stages 0 and 1 resident
    __syncthreads();

    uint32_t afA[4][4], bfA[2][4], afB[4][4], bfB[2][4];
    ldfrags(smem_u32 + SM_STAGE0, 0, afA, bfA);

    for (int kt = 0; kt < NCHUNK; kt++) {
        const uint32_t stc = smem_u32 + SM_STAGE0 + (kt % STAGES) * STAGE_B;
        if (kt + 4 < NCHUNK) load_stage(kt + 4, (kt + 4) % STAGES);

        // half 0: prefetch kk=16 frags, mma on kk=0 frags
        ldfrags(stc, 16, afB, bfB);
        do_mma(afA, bfA);

        // half 1: prefetch next stage kk=0 frags (stage kt+1 resident), mma kk=16
        if (kt + 1 < NCHUNK) {
            const uint32_t stn = smem_u32 + SM_STAGE0 + ((kt + 1) % STAGES) * STAGE_B;
            ldfrags(stn, 0, afA, bfA);
        }
        do_mma(afB, bfB);

        // invariant for kt+1: stages kt+1, kt+2 resident
        if (kt + 1 < NCHUNK) {
            CP_WAIT(2);
            __syncthreads();
        }
    }

    // ---------------- epilogue ----------------
    const int groupID = lane >> 2;
    const int tidg    = lane & 3;
    #pragma unroll
    for (int i = 0; i < 4; i++) {
        const int m0 = block_m + warp_m * 64 + i * 16 + groupID;
        #pragma unroll
        for (int t = 0; t < 4; t++) {
            const int ln = warp_n * 32 + t * 8 + tidg * 2;
            const float sc0 = s_scale[ln],     mo0 = s_memo[ln];
            const float sc1 = s_scale[ln + 1], mo1 = s_memo[ln + 1];
            float2 o0, o1;
            o0.x = fmaf(acc[i][t][0], sc0, mo0);
            o0.y = fmaf(acc[i][t][1], sc1, mo1);
            o1.x = fmaf(acc[i][t][2], sc0, mo0);
            o1.y = fmaf(acc[i][t][3], sc1, mo1);
            *reinterpret_cast<float2*>(C + (size_t)m0 * DOUT + block_n + ln)       = o0;
            *reinterpret_cast<float2*>(C + (size_t)(m0 + 8) * DOUT + block_n + ln) = o1;
        }
    }
}

// ---------------------------------------------------------------- host launch
extern "C" void kernel_launch(void* const* d_in, const int* in_sizes, int n_in,
                              void* d_out, int out_size) {
    const float* x      = (const float*)d_in[0];  // [B,S,DIN]
    const float* wlat   = (const float*)d_in[1];  // [DOUT,DIN]
    const float* wscale = (const float*)d_in[2];  // [DOUT,1]
    const float* mkeys  = (const float*)d_in[3];  // [CAP,DIN]
    const float* mvals  = (const float*)d_in[4];  // [CAP,DOUT]
    float* out = (float*)d_out;                   // [B,S,DOUT]
    (void)in_sizes; (void)n_in; (void)out_size;

    void *p_xh, *p_wh;
    cudaGetSymbolAddress(&p_xh, g_xh);
    cudaGetSymbolAddress(&p_wh, g_wh);

    // conversions (8 elems/thread)
    {
        int n8 = MTOT * DIN / 8;
        convert_single_kernel<<<n8 / 256, 256>>>(x, (__half*)p_xh, n8);
        int w8 = DOUT * DIN / 8;
        convert_single_kernel<<<w8 / 256, 256>>>(wlat, (__half*)p_wh, w8);
    }

    // associative memory path
    scores_kernel<<<CAP, 256>>>(mkeys, x);
    memout_fused_kernel<<<DOUT / 32, 256>>>(mvals);

    // main GEMM
    cudaFuncSetAttribute(gemm_mma_kernel, cudaFuncAttributeMaxDynamicSharedMemorySize, GEMM_SMEM);
    dim3 grid(MTOT / BM, DOUT / BN);   // 64 x 16 (m fast)
    gemm_mma_kernel<<<grid, NTHREADS, GEMM_SMEM>>>(wscale, out);
}

// round 14
// speedup vs baseline: 1.2324x; 1.0702x over previous
#include <cuda_runtime.h>
#include <cuda_fp16.h>
#include <cstdint>

// ---------------------------------------------------------------- shapes
#define BB   4
#define SS   2048
#define DIN  4096
#define DOUT 4096
#define CAP  1024
#define MTOT (BB * SS)       // 8192

// GEMM tiling
#define BM 128
#define BN 256
#define BK 64                 // fp16 elems per stage chunk
#define NCHUNK (DIN / BK)     // 64
#define STAGES 4
#define NTHREADS 512

// smem geometry: rows padded 64 -> 72 halves (144B pitch, conflict-free ldmatrix)
#define ROWP 72
#define A_BUF_B (BM * ROWP * 2)     // 18432
#define B_BUF_B (BN * ROWP * 2)     // 36864
#define STAGE_B (A_BUF_B + B_BUF_B)           // 55296
#define SM_STAGE0 2048
#define GEMM_SMEM (SM_STAGE0 + STAGES * STAGE_B)   // 223232

// ---------------------------------------------------------------- scratch
__device__ float g_scores[CAP];
__device__ float g_mem_out[DOUT];
__device__ __align__(1024) __half g_xh[(size_t)MTOT * DIN];
__device__ __align__(1024) __half g_wh[(size_t)DOUT * DIN];

// ---------------------------------------------------------------- PTX helpers
__device__ __forceinline__ uint32_t smem_to_u32(const void* p) {
    uint32_t a;
    asm("{ .reg .u64 t; cvta.to.shared.u64 t, %1; cvt.u32.u64 %0, t; }" : "=r"(a) : "l"(p));
    return a;
}
__device__ __forceinline__ void cp16(uint32_t dst, const void* src) {
    asm volatile("cp.async.cg.shared.global [%0], [%1], 16;" :: "r"(dst), "l"(src));
}
#define CP_COMMIT() asm volatile("cp.async.commit_group;" ::: "memory")
#define CP_WAIT(n)  asm volatile("cp.async.wait_group %0;" :: "n"(n) : "memory")

__device__ __forceinline__ void ldsm_x4(uint32_t* r, uint32_t addr) {
    asm volatile("ldmatrix.sync.aligned.m8n8.x4.shared.b16 {%0,%1,%2,%3}, [%4];"
        : "=r"(r[0]), "=r"(r[1]), "=r"(r[2]), "=r"(r[3]) : "r"(addr));
}
__device__ __forceinline__ void mma16816(float* c, const uint32_t* a, const uint32_t* b) {
    asm volatile("mma.sync.aligned.m16n8k16.row.col.f32.f16.f16.f32 "
        "{%0,%1,%2,%3}, {%4,%5,%6,%7}, {%8,%9}, {%0,%1,%2,%3};"
        : "+f"(c[0]), "+f"(c[1]), "+f"(c[2]), "+f"(c[3])
        : "r"(a[0]), "r"(a[1]), "r"(a[2]), "r"(a[3]), "r"(b[0]), "r"(b[1]));
}

// ---------------------------------------------------------------- small kernels
__global__ void scores_kernel(const float* __restrict__ keys, const float* __restrict__ x) {
    const int c = blockIdx.x;
    const float4* row = reinterpret_cast<const float4*>(keys + (size_t)c * DIN);
    const float4* q   = reinterpret_cast<const float4*>(x);
    float sum = 0.f;
    for (int i = threadIdx.x; i < DIN / 4; i += 256) {
        float4 a = row[i], b = q[i];
        sum += a.x * b.x + a.y * b.y + a.z * b.z + a.w * b.w;
    }
    #pragma unroll
    for (int off = 16; off; off >>= 1) sum += __shfl_down_sync(0xffffffffu, sum, off);
    __shared__ float red[8];
    if ((threadIdx.x & 31) == 0) red[threadIdx.x >> 5] = sum;
    __syncthreads();
    if (threadIdx.x < 8) {
        float v = red[threadIdx.x];
        #pragma unroll
        for (int off = 4; off; off >>= 1) v += __shfl_down_sync(0xffu, v, off);
        if (threadIdx.x == 0) g_scores[c] = v;
    }
}

// fused softmax + memout. grid=128 blocks, 256 threads.
__global__ void memout_fused_kernel(const float* __restrict__ vals) {
    __shared__ float s_attn[CAP];
    __shared__ float red[8];
    __shared__ float s_part[8][32];
    const int t = threadIdx.x;
    const int lane = t & 31;
    const int wrp  = t >> 5;

    float v[4], m = -1e30f;
    #pragma unroll
    for (int j = 0; j < 4; j++) { v[j] = g_scores[t * 4 + j]; m = fmaxf(m, v[j]); }
    #pragma unroll
    for (int off = 16; off; off >>= 1) m = fmaxf(m, __shfl_xor_sync(0xffffffffu, m, off));
    if (lane == 0) red[wrp] = m;
    __syncthreads();
    if (t < 8) {
        float w = red[t];
        #pragma unroll
        for (int off = 4; off; off >>= 1) w = fmaxf(w, __shfl_xor_sync(0xffu, w, off));
        red[t] = w;
    }
    __syncthreads();
    m = red[0];
    __syncthreads();
    float s = 0.f;
    #pragma unroll
    for (int j = 0; j < 4; j++) { v[j] = expf(v[j] - m); s += v[j]; }
    #pragma unroll
    for (int off = 16; off; off >>= 1) s += __shfl_xor_sync(0xffffffffu, s, off);
    if (lane == 0) red[wrp] = s;
    __syncthreads();
    if (t < 8) {
        float w = red[t];
        #pragma unroll
        for (int off = 4; off; off >>= 1) w += __shfl_xor_sync(0xffu, w, off);
        red[t] = w;
    }
    __syncthreads();
    const float inv = 1.f / red[0];
    #pragma unroll
    for (int j = 0; j < 4; j++) s_attn[t * 4 + j] = v[j] * inv;
    __syncthreads();

    const int o   = blockIdx.x * 32 + (t & 31);
    const int seg = t >> 5;
    const int c0  = seg * 128;
    float acc = 0.f;
    #pragma unroll 4
    for (int c = 0; c < 128; c++)
        acc = fmaf(s_attn[c0 + c], vals[(size_t)(c0 + c) * DOUT + o], acc);
    s_part[seg][t & 31] = acc;
    __syncthreads();
    if (t < 32) {
        float tot = 0.f;
        #pragma unroll
        for (int g = 0; g < 8; g++) tot += s_part[g][t];
        g_mem_out[blockIdx.x * 32 + t] = tot;
    }
}

// fused fp32 -> fp16 cast for both x and w (one launch)
__global__ void convert_both_kernel(const float* __restrict__ x,
                                    const float* __restrict__ w,
                                    __half* __restrict__ xh,
                                    __half* __restrict__ wh, int n8x, int n8tot) {
    int i = blockIdx.x * blockDim.x + threadIdx.x;
    if (i >= n8tot) return;
    const float* src; __half* dst; int j;
    if (i < n8x) { src = x; dst = xh; j = i; }
    else         { src = w; dst = wh; j = i - n8x; }
    float4 v0 = reinterpret_cast<const float4*>(src)[j * 2 + 0];
    float4 v1 = reinterpret_cast<const float4*>(src)[j * 2 + 1];
    __half2 h[4];
    h[0].x = __float2half_rn(v0.x); h[0].y = __float2half_rn(v0.y);
    h[1].x = __float2half_rn(v0.z); h[1].y = __float2half_rn(v0.w);
    h[2].x = __float2half_rn(v1.x); h[2].y = __float2half_rn(v1.y);
    h[3].x = __float2half_rn(v1.z); h[3].y = __float2half_rn(v1.w);
    reinterpret_cast<uint4*>(dst)[j] = *reinterpret_cast<uint4*>(h);
}

// ---------------------------------------------------------------- main GEMM
// C[m,n] = scale[n] * (xh[m,:].wh[n,:]) + 0.01*mem_out[n]
// 512 threads, warps 2(m) x 8(n), warp tile 64x32. BK=64, 4-stage cp.async.
__global__ __launch_bounds__(NTHREADS, 1)
void gemm_mma_kernel(const float* __restrict__ scales, float* __restrict__ C) {
    extern __shared__ char smem[];
    const uint32_t smem_u32 = smem_to_u32(smem);
    float* s_scale = reinterpret_cast<float*>(smem);
    float* s_memo  = reinterpret_cast<float*>(smem + 1024);

    const int tid  = threadIdx.x;
    const int wid  = tid >> 5;
    const int lane = tid & 31;
    const int warp_m = wid & 1;        // 2 strips of 64 rows
    const int warp_n = wid >> 1;       // 8 strips of 32 cols
    const int block_m = blockIdx.x * BM;   // m fast -> consecutive CTAs share W tile
    const int block_n = blockIdx.y * BN;

    for (int i = tid; i < BN; i += NTHREADS) {
        s_scale[i] = scales[block_n + i];
        s_memo[i]  = 0.01f * g_mem_out[block_n + i];
    }

    const __half* gXh = g_xh + (size_t)block_m * DIN;
    const __half* gWh = g_wh + (size_t)block_n * DIN;

    // A: 1024 chunks of 16B -> 2/thread; B: 2048 chunks -> 4/thread
    auto load_stage = [&](int kt, int s) {
        const int k0 = kt * BK;
        const uint32_t st = smem_u32 + SM_STAGE0 + s * STAGE_B;
        const uint32_t sA = st;
        const uint32_t sB = st + A_BUF_B;
        #pragma unroll
        for (int j = 0; j < 2; j++) {
            int idx = tid + NTHREADS * j;
            int row = idx >> 3, c = idx & 7;
            size_t go = (size_t)row * DIN + k0 + c * 8;
            uint32_t so = row * (ROWP * 2) + c * 16;
            cp16(sA + so, gXh + go);
        }
        #pragma unroll
        for (int j = 0; j < 4; j++) {
            int idx = tid + NTHREADS * j;
            int row = idx >> 3, c = idx & 7;
            size_t go = (size_t)row * DIN + k0 + c * 8;
            uint32_t so = row * (ROWP * 2) + c * 16;
            cp16(sB + so, gWh + go);
        }
        CP_COMMIT();
    };

    float acc[4][4][4];
    #pragma unroll
    for (int i = 0; i < 4; i++)
        #pragma unroll
        for (int t = 0; t < 4; t++)
            #pragma unroll
            for (int r = 0; r < 4; r++) acc[i][t][r] = 0.f;

    const int a_row = lane & 15;
    const int a_k   = (lane >> 4) * 8;
    const int b_row = (lane & 7) + ((lane >> 4) << 3);
    const int b_k   = ((lane >> 3) & 1) * 8;

    auto ldfrags = [&](uint32_t st, int kk, uint32_t af[4][4], uint32_t bf[2][4]) {
        const uint32_t sA = st;
        const uint32_t sB = st + A_BUF_B;
        #pragma unroll
        for (int i = 0; i < 4; i++) {
            uint32_t off = (uint32_t)(warp_m * 64 + i * 16 + a_row) * (ROWP * 2)
                         + (kk + a_k) * 2;
            ldsm_x4(af[i], sA + off);
        }
        #pragma unroll
        for (int p = 0; p < 2; p++) {
            uint32_t off = (uint32_t)(warp_n * 32 + p * 16 + b_row) * (ROWP * 2)
                         + (kk + b_k) * 2;
            ldsm_x4(bf[p], sB + off);
        }
    };

    auto do_mma = [&](uint32_t af[4][4], uint32_t bf[2][4]) {
        #pragma unroll
        for (int p = 0; p < 2; p++) {
            #pragma unroll
            for (int i = 0; i < 4; i++) {
                mma16816(acc[i][2 * p],     af[i], bf[p]);
                mma16816(acc[i][2 * p + 1], af[i], bf[p] + 2);
            }
        }
    };

    // prologue: fill 3 of 4 stages; ensure stages 0,1 resident
    load_stage(0, 0);
    load_stage(1, 1);
    load_stage(2, 2);
    CP_WAIT(1);
    __syncthreads();

    uint32_t afA[4][4], bfA[2][4], afB[4][4], bfB[2][4];
    ldfrags(smem_u32 + SM_STAGE0, 0, afA, bfA);

    for (int kt = 0; kt < NCHUNK; kt++) {
        const uint32_t stc = smem_u32 + SM_STAGE0 + (kt % STAGES) * STAGE_B;
        if (kt + 3 < NCHUNK) load_stage(kt + 3, (kt + 3) % STAGES);

        // 4 kk-steps, register double-buffered
        ldfrags(stc, 16, afB, bfB);
        do_mma(afA, bfA);
        ldfrags(stc, 32, afA, bfA);
        do_mma(afB, bfB);
        ldfrags(stc, 48, afB, bfB);
        do_mma(afA, bfA);
        if (kt + 1 < NCHUNK) {
            const uint32_t stn = smem_u32 + SM_STAGE0 + ((kt + 1) % STAGES) * STAGE_B;
            ldfrags(stn, 0, afA, bfA);     // stage kt+1 resident by invariant
        }
        do_mma(afB, bfB);

        // invariant for iter kt+1: stages kt+1 (already) and kt+2 resident
        if (kt + 1 < NCHUNK) {
            CP_WAIT(1);
            __syncthreads();
        }
    }

    // ---------------- epilogue ----------------
    const int groupID = lane >> 2;
    const int tidg    = lane & 3;
    #pragma unroll
    for (int i = 0; i < 4; i++) {
        const int m0 = block_m + warp_m * 64 + i * 16 + groupID;
        #pragma unroll
        for (int t = 0; t < 4; t++) {
            const int ln = warp_n * 32 + t * 8 + tidg * 2;
            const float sc0 = s_scale[ln],     mo0 = s_memo[ln];
            const float sc1 = s_scale[ln + 1], mo1 = s_memo[ln + 1];
            float2 o0, o1;
            o0.x = fmaf(acc[i][t][0], sc0, mo0);
            o0.y = fmaf(acc[i][t][1], sc1, mo1);
            o1.x = fmaf(acc[i][t][2], sc0, mo0);
            o1.y = fmaf(acc[i][t][3], sc1, mo1);
            *reinterpret_cast<float2*>(C + (size_t)m0 * DOUT + block_n + ln)       = o0;
            *reinterpret_cast<float2*>(C + (size_t)(m0 + 8) * DOUT + block_n + ln) = o1;
        }
    }
}

// ---------------------------------------------------------------- host launch
extern "C" void kernel_launch(void* const* d_in, const int* in_sizes, int n_in,
                              void* d_out, int out_size) {
    const float* x      = (const float*)d_in[0];  // [B,S,DIN]
    const float* wlat   = (const float*)d_in[1];  // [DOUT,DIN]
    const float* wscale = (const float*)d_in[2];  // [DOUT,1]
    const float* mkeys  = (const float*)d_in[3];  // [CAP,DIN]
    const float* mvals  = (const float*)d_in[4];  // [CAP,DOUT]
    float* out = (float*)d_out;                   // [B,S,DOUT]
    (void)in_sizes; (void)n_in; (void)out_size;

    void *p_xh, *p_wh;
    cudaGetSymbolAddress(&p_xh, g_xh);
    cudaGetSymbolAddress(&p_wh, g_wh);

    // fused conversion (one launch)
    {
        int n8x = MTOT * DIN / 8;
        int n8t = n8x + DOUT * DIN / 8;
        convert_both_kernel<<<(n8t + 255) / 256, 256>>>(x, wlat, (__half*)p_xh, (__half*)p_wh,
                                                        n8x, n8t);
    }

    // associative memory path
    scores_kernel<<<CAP, 256>>>(mkeys, x);
    memout_fused_kernel<<<DOUT / 32, 256>>>(mvals);

    // main GEMM
    cudaFuncSetAttribute(gemm_mma_kernel, cudaFuncAttributeMaxDynamicSharedMemorySize, GEMM_SMEM);
    dim3 grid(MTOT / BM, DOUT / BN);   // 64 x 16 (m fast)
    gemm_mma_kernel<<<grid, NTHREADS, GEMM_SMEM>>>(wscale, out);
}

// round 15
// speedup vs baseline: 1.3146x; 1.0667x over previous
#include <cuda_runtime.h>
#include <cuda_fp16.h>
#include <cstdint>

// ---------------------------------------------------------------- shapes
#define BB   4
#define SS   2048
#define DIN  4096
#define DOUT 4096
#define CAP  1024
#define MTOT (BB * SS)       // 8192

// GEMM tiling: 128x128 CTA tile, 2 CTAs per SM
#define BM 128
#define BN 128
#define BK 64                 // fp16 elems per stage chunk
#define NCHUNK (DIN / BK)     // 64
#define STAGES 3
#define NTHREADS 256

// smem geometry: rows padded 64 -> 72 halves (144B pitch, conflict-free ldmatrix)
#define ROWP 72
#define A_BUF_B (BM * ROWP * 2)     // 18432
#define B_BUF_B (BN * ROWP * 2)     // 18432
#define STAGE_B (A_BUF_B + B_BUF_B)           // 36864
#define SM_STAGE0 2048
#define GEMM_SMEM (SM_STAGE0 + STAGES * STAGE_B)   // 112640 -> 2 CTAs/SM

// ---------------------------------------------------------------- scratch
__device__ float g_scores[CAP];
__device__ float g_mem_out[DOUT];
__device__ __align__(1024) __half g_xh[(size_t)MTOT * DIN];
__device__ __align__(1024) __half g_wh[(size_t)DOUT * DIN];

// ---------------------------------------------------------------- PTX helpers
__device__ __forceinline__ uint32_t smem_to_u32(const void* p) {
    uint32_t a;
    asm("{ .reg .u64 t; cvta.to.shared.u64 t, %1; cvt.u32.u64 %0, t; }" : "=r"(a) : "l"(p));
    return a;
}
__device__ __forceinline__ void cp16(uint32_t dst, const void* src) {
    asm volatile("cp.async.cg.shared.global [%0], [%1], 16;" :: "r"(dst), "l"(src));
}
#define CP_COMMIT() asm volatile("cp.async.commit_group;" ::: "memory")
#define CP_WAIT(n)  asm volatile("cp.async.wait_group %0;" :: "n"(n) : "memory")

__device__ __forceinline__ void ldsm_x4(uint32_t* r, uint32_t addr) {
    asm volatile("ldmatrix.sync.aligned.m8n8.x4.shared.b16 {%0,%1,%2,%3}, [%4];"
        : "=r"(r[0]), "=r"(r[1]), "=r"(r[2]), "=r"(r[3]) : "r"(addr));
}
__device__ __forceinline__ void mma16816(float* c, const uint32_t* a, const uint32_t* b) {
    asm volatile("mma.sync.aligned.m16n8k16.row.col.f32.f16.f16.f32 "
        "{%0,%1,%2,%3}, {%4,%5,%6,%7}, {%8,%9}, {%0,%1,%2,%3};"
        : "+f"(c[0]), "+f"(c[1]), "+f"(c[2]), "+f"(c[3])
        : "r"(a[0]), "r"(a[1]), "r"(a[2]), "r"(a[3]), "r"(b[0]), "r"(b[1]));
}

// ---------------------------------------------------------------- small kernels
__global__ void scores_kernel(const float* __restrict__ keys, const float* __restrict__ x) {
    const int c = blockIdx.x;
    const float4* row = reinterpret_cast<const float4*>(keys + (size_t)c * DIN);
    const float4* q   = reinterpret_cast<const float4*>(x);
    float sum = 0.f;
    for (int i = threadIdx.x; i < DIN / 4; i += 256) {
        float4 a = row[i], b = q[i];
        sum += a.x * b.x + a.y * b.y + a.z * b.z + a.w * b.w;
    }
    #pragma unroll
    for (int off = 16; off; off >>= 1) sum += __shfl_down_sync(0xffffffffu, sum, off);
    __shared__ float red[8];
    if ((threadIdx.x & 31) == 0) red[threadIdx.x >> 5] = sum;
    __syncthreads();
    if (threadIdx.x < 8) {
        float v = red[threadIdx.x];
        #pragma unroll
        for (int off = 4; off; off >>= 1) v += __shfl_down_sync(0xffu, v, off);
        if (threadIdx.x == 0) g_scores[c] = v;
    }
}

// fused softmax + memout. grid=128 blocks, 256 threads.
__global__ void memout_fused_kernel(const float* __restrict__ vals) {
    __shared__ float s_attn[CAP];
    __shared__ float red[8];
    __shared__ float s_part[8][32];
    const int t = threadIdx.x;
    const int lane = t & 31;
    const int wrp  = t >> 5;

    float v[4], m = -1e30f;
    #pragma unroll
    for (int j = 0; j < 4; j++) { v[j] = g_scores[t * 4 + j]; m = fmaxf(m, v[j]); }
    #pragma unroll
    for (int off = 16; off; off >>= 1) m = fmaxf(m, __shfl_xor_sync(0xffffffffu, m, off));
    if (lane == 0) red[wrp] = m;
    __syncthreads();
    if (t < 8) {
        float w = red[t];
        #pragma unroll
        for (int off = 4; off; off >>= 1) w = fmaxf(w, __shfl_xor_sync(0xffu, w, off));
        red[t] = w;
    }
    __syncthreads();
    m = red[0];
    __syncthreads();
    float s = 0.f;
    #pragma unroll
    for (int j = 0; j < 4; j++) { v[j] = expf(v[j] - m); s += v[j]; }
    #pragma unroll
    for (int off = 16; off; off >>= 1) s += __shfl_xor_sync(0xffffffffu, s, off);
    if (lane == 0) red[wrp] = s;
    __syncthreads();
    if (t < 8) {
        float w = red[t];
        #pragma unroll
        for (int off = 4; off; off >>= 1) w += __shfl_xor_sync(0xffu, w, off);
        red[t] = w;
    }
    __syncthreads();
    const float inv = 1.f / red[0];
    #pragma unroll
    for (int j = 0; j < 4; j++) s_attn[t * 4 + j] = v[j] * inv;
    __syncthreads();

    const int o   = blockIdx.x * 32 + (t & 31);
    const int seg = t >> 5;
    const int c0  = seg * 128;
    float acc = 0.f;
    #pragma unroll 4
    for (int c = 0; c < 128; c++)
        acc = fmaf(s_attn[c0 + c], vals[(size_t)(c0 + c) * DOUT + o], acc);
    s_part[seg][t & 31] = acc;
    __syncthreads();
    if (t < 32) {
        float tot = 0.f;
        #pragma unroll
        for (int g = 0; g < 8; g++) tot += s_part[g][t];
        g_mem_out[blockIdx.x * 32 + t] = tot;
    }
}

// fused fp32 -> fp16 cast for both x and w (one launch)
__global__ void convert_both_kernel(const float* __restrict__ x,
                                    const float* __restrict__ w,
                                    __half* __restrict__ xh,
                                    __half* __restrict__ wh, int n8x, int n8tot) {
    int i = blockIdx.x * blockDim.x + threadIdx.x;
    if (i >= n8tot) return;
    const float* src; __half* dst; int j;
    if (i < n8x) { src = x; dst = xh; j = i; }
    else         { src = w; dst = wh; j = i - n8x; }
    float4 v0 = reinterpret_cast<const float4*>(src)[j * 2 + 0];
    float4 v1 = reinterpret_cast<const float4*>(src)[j * 2 + 1];
    __half2 h[4];
    h[0].x = __float2half_rn(v0.x); h[0].y = __float2half_rn(v0.y);
    h[1].x = __float2half_rn(v0.z); h[1].y = __float2half_rn(v0.w);
    h[2].x = __float2half_rn(v1.x); h[2].y = __float2half_rn(v1.y);
    h[3].x = __float2half_rn(v1.z); h[3].y = __float2half_rn(v1.w);
    reinterpret_cast<uint4*>(dst)[j] = *reinterpret_cast<uint4*>(h);
}

// ---------------------------------------------------------------- main GEMM
// C[m,n] = scale[n] * (xh[m,:].wh[n,:]) + 0.01*mem_out[n]
// 256 threads, warps 2(m) x 4(n), warp tile 64x32. BK=64, 3-stage cp.async.
// 2 CTAs per SM -> cross-CTA overlap hides barrier/ldsm bubbles.
__global__ __launch_bounds__(NTHREADS, 2)
void gemm_mma_kernel(const float* __restrict__ scales, float* __restrict__ C) {
    extern __shared__ char smem[];
    const uint32_t smem_u32 = smem_to_u32(smem);
    float* s_scale = reinterpret_cast<float*>(smem);
    float* s_memo  = reinterpret_cast<float*>(smem + 512);

    const int tid  = threadIdx.x;
    const int wid  = tid >> 5;
    const int lane = tid & 31;
    const int warp_m = wid & 1;        // 2 strips of 64 rows
    const int warp_n = wid >> 1;       // 4 strips of 32 cols
    const int block_m = blockIdx.x * BM;   // m fast -> consecutive CTAs share W tile
    const int block_n = blockIdx.y * BN;

    for (int i = tid; i < BN; i += NTHREADS) {
        s_scale[i] = scales[block_n + i];
        s_memo[i]  = 0.01f * g_mem_out[block_n + i];
    }

    const __half* gXh = g_xh + (size_t)block_m * DIN;
    const __half* gWh = g_wh + (size_t)block_n * DIN;

    // A and B: each 128 rows x 8 chunks of 16B = 1024 chunks -> 4/thread
    auto load_stage = [&](int kt, int s) {
        const int k0 = kt * BK;
        const uint32_t st = smem_u32 + SM_STAGE0 + s * STAGE_B;
        const uint32_t sA = st;
        const uint32_t sB = st + A_BUF_B;
        #pragma unroll
        for (int j = 0; j < 4; j++) {
            int idx = tid + NTHREADS * j;
            int row = idx >> 3, c = idx & 7;
            size_t go = (size_t)row * DIN + k0 + c * 8;
            uint32_t so = row * (ROWP * 2) + c * 16;
            cp16(sA + so, gXh + go);
        }
        #pragma unroll
        for (int j = 0; j < 4; j++) {
            int idx = tid + NTHREADS * j;
            int row = idx >> 3, c = idx & 7;
            size_t go = (size_t)row * DIN + k0 + c * 8;
            uint32_t so = row * (ROWP * 2) + c * 16;
            cp16(sB + so, gWh + go);
        }
        CP_COMMIT();
    };

    float acc[4][4][4];
    #pragma unroll
    for (int i = 0; i < 4; i++)
        #pragma unroll
        for (int t = 0; t < 4; t++)
            #pragma unroll
            for (int r = 0; r < 4; r++) acc[i][t][r] = 0.f;

    const int a_row = lane & 15;
    const int a_k   = (lane >> 4) * 8;
    const int b_row = (lane & 7) + ((lane >> 4) << 3);
    const int b_k   = ((lane >> 3) & 1) * 8;

    auto ldfrags = [&](uint32_t st, int kk, uint32_t af[4][4], uint32_t bf[2][4]) {
        const uint32_t sA = st;
        const uint32_t sB = st + A_BUF_B;
        #pragma unroll
        for (int i = 0; i < 4; i++) {
            uint32_t off = (uint32_t)(warp_m * 64 + i * 16 + a_row) * (ROWP * 2)
                         + (kk + a_k) * 2;
            ldsm_x4(af[i], sA + off);
        }
        #pragma unroll
        for (int p = 0; p < 2; p++) {
            uint32_t off = (uint32_t)(warp_n * 32 + p * 16 + b_row) * (ROWP * 2)
                         + (kk + b_k) * 2;
            ldsm_x4(bf[p], sB + off);
        }
    };

    auto do_mma = [&](uint32_t af[4][4], uint32_t bf[2][4]) {
        #pragma unroll
        for (int p = 0; p < 2; p++) {
            #pragma unroll
            for (int i = 0; i < 4; i++) {
                mma16816(acc[i][2 * p],     af[i], bf[p]);
                mma16816(acc[i][2 * p + 1], af[i], bf[p] + 2);
            }
        }
    };

    // prologue: 2 of 3 stages loaded and resident
    load_stage(0, 0);
    load_stage(1, 1);
    CP_WAIT(0);
    __syncthreads();

    uint32_t afA[4][4], bfA[2][4], afB[4][4], bfB[2][4];
    ldfrags(smem_u32 + SM_STAGE0, 0, afA, bfA);

    for (int kt = 0; kt < NCHUNK; kt++) {
        const uint32_t stc = smem_u32 + SM_STAGE0 + (kt % STAGES) * STAGE_B;
        const bool issued = (kt + 2 < NCHUNK);
        if (issued) load_stage(kt + 2, (kt + 2) % STAGES);

        // 4 kk-steps, register double-buffered
        ldfrags(stc, 16, afB, bfB);
        do_mma(afA, bfA);
        ldfrags(stc, 32, afA, bfA);
        do_mma(afB, bfB);
        ldfrags(stc, 48, afB, bfB);
        do_mma(afA, bfA);

        if (kt + 1 < NCHUNK) {
            // make stage kt+1 resident BEFORE prefetching its fragments;
            // sync also separates readers of stage kt from next iter's writer
            if (issued) { CP_WAIT(1); } else { CP_WAIT(0); }
            __syncthreads();
            const uint32_t stn = smem_u32 + SM_STAGE0 + ((kt + 1) % STAGES) * STAGE_B;
            ldfrags(stn, 0, afA, bfA);
        }
        do_mma(afB, bfB);
    }

    // ---------------- epilogue ----------------
    const int groupID = lane >> 2;
    const int tidg    = lane & 3;
    #pragma unroll
    for (int i = 0; i < 4; i++) {
        const int m0 = block_m + warp_m * 64 + i * 16 + groupID;
        #pragma unroll
        for (int t = 0; t < 4; t++) {
            const int ln = warp_n * 32 + t * 8 + tidg * 2;
            const float sc0 = s_scale[ln],     mo0 = s_memo[ln];
            const float sc1 = s_scale[ln + 1], mo1 = s_memo[ln + 1];
            float2 o0, o1;
            o0.x = fmaf(acc[i][t][0], sc0, mo0);
            o0.y = fmaf(acc[i][t][1], sc1, mo1);
            o1.x = fmaf(acc[i][t][2], sc0, mo0);
            o1.y = fmaf(acc[i][t][3], sc1, mo1);
            *reinterpret_cast<float2*>(C + (size_t)m0 * DOUT + block_n + ln)       = o0;
            *reinterpret_cast<float2*>(C + (size_t)(m0 + 8) * DOUT + block_n + ln) = o1;
        }
    }
}

// ---------------------------------------------------------------- host launch
extern "C" void kernel_launch(void* const* d_in, const int* in_sizes, int n_in,
                              void* d_out, int out_size) {
    const float* x      = (const float*)d_in[0];  // [B,S,DIN]
    const float* wlat   = (const float*)d_in[1];  // [DOUT,DIN]
    const float* wscale = (const float*)d_in[2];  // [DOUT,1]
    const float* mkeys  = (const float*)d_in[3];  // [CAP,DIN]
    const float* mvals  = (const float*)d_in[4];  // [CAP,DOUT]
    float* out = (float*)d_out;                   // [B,S,DOUT]
    (void)in_sizes; (void)n_in; (void)out_size;

    void *p_xh, *p_wh;
    cudaGetSymbolAddress(&p_xh, g_xh);
    cudaGetSymbolAddress(&p_wh, g_wh);

    // fused conversion (one launch)
    {
        int n8x = MTOT * DIN / 8;
        int n8t = n8x + DOUT * DIN / 8;
        convert_both_kernel<<<(n8t + 255) / 256, 256>>>(x, wlat, (__half*)p_xh, (__half*)p_wh,
                                                        n8x, n8t);
    }

    // associative memory path
    scores_kernel<<<CAP, 256>>>(mkeys, x);
    memout_fused_kernel<<<DOUT / 32, 256>>>(mvals);

    // main GEMM
    cudaFuncSetAttribute(gemm_mma_kernel, cudaFuncAttributeMaxDynamicSharedMemorySize, GEMM_SMEM);
    dim3 grid(MTOT / BM, DOUT / BN);   // 64 x 32 (m fast)
    gemm_mma_kernel<<<grid, NTHREADS, GEMM_SMEM>>>(wscale, out);
}

// round 16
// speedup vs baseline: 1.3672x; 1.0400x over previous
#include <cuda_runtime.h>
#include <cuda_fp16.h>
#include <cstdint>

// ---------------------------------------------------------------- shapes
#define BB   4
#define SS   2048
#define DIN  4096
#define DOUT 4096
#define CAP  1024
#define MTOT (BB * SS)       // 8192

// GEMM tiling: CTA 128x128, 256 threads, warps 2(m) x 4(n), warp tile 64x32
#define BM 128
#define BN 128
#define NTHREADS 256
#define NK16 (DIN / 16)      // 256 k-tiles
#define NM16 (MTOT / 16)     // 512
#define NN16 (DOUT / 16)     // 256

// ---------------------------------------------------------------- scratch
// Fragment-permuted fp16 copies:
//  x: tile (m16, k16) at offset (m16*NK16 + k16)*256 halves; lane l owns 16B.
//  w: tile (n16, k16) at offset (n16*NK16 + k16)*256 halves.
__device__ float g_scores[CAP];
__device__ float g_mem_out[DOUT];
__device__ __align__(1024) __half g_xp[(size_t)MTOT * DIN];
__device__ __align__(1024) __half g_wp[(size_t)DOUT * DIN];

// ---------------------------------------------------------------- PTX helpers
__device__ __forceinline__ void mma16816(float* c, const uint32_t* a, const uint32_t* b) {
    asm volatile("mma.sync.aligned.m16n8k16.row.col.f32.f16.f16.f32 "
        "{%0,%1,%2,%3}, {%4,%5,%6,%7}, {%8,%9}, {%0,%1,%2,%3};"
        : "+f"(c[0]), "+f"(c[1]), "+f"(c[2]), "+f"(c[3])
        : "r"(a[0]), "r"(a[1]), "r"(a[2]), "r"(a[3]), "r"(b[0]), "r"(b[1]));
}

// ---------------------------------------------------------------- small kernels
__global__ void scores_kernel(const float* __restrict__ keys, const float* __restrict__ x) {
    const int c = blockIdx.x;
    const float4* row = reinterpret_cast<const float4*>(keys + (size_t)c * DIN);
    const float4* q   = reinterpret_cast<const float4*>(x);
    float sum = 0.f;
    for (int i = threadIdx.x; i < DIN / 4; i += 256) {
        float4 a = row[i], b = q[i];
        sum += a.x * b.x + a.y * b.y + a.z * b.z + a.w * b.w;
    }
    #pragma unroll
    for (int off = 16; off; off >>= 1) sum += __shfl_down_sync(0xffffffffu, sum, off);
    __shared__ float red[8];
    if ((threadIdx.x & 31) == 0) red[threadIdx.x >> 5] = sum;
    __syncthreads();
    if (threadIdx.x < 8) {
        float v = red[threadIdx.x];
        #pragma unroll
        for (int off = 4; off; off >>= 1) v += __shfl_down_sync(0xffu, v, off);
        if (threadIdx.x == 0) g_scores[c] = v;
    }
}

// fused softmax + memout. grid=128 blocks, 256 threads.
__global__ void memout_fused_kernel(const float* __restrict__ vals) {
    __shared__ float s_attn[CAP];
    __shared__ float red[8];
    __shared__ float s_part[8][32];
    const int t = threadIdx.x;
    const int lane = t & 31;
    const int wrp  = t >> 5;

    float v[4], m = -1e30f;
    #pragma unroll
    for (int j = 0; j < 4; j++) { v[j] = g_scores[t * 4 + j]; m = fmaxf(m, v[j]); }
    #pragma unroll
    for (int off = 16; off; off >>= 1) m = fmaxf(m, __shfl_xor_sync(0xffffffffu, m, off));
    if (lane == 0) red[wrp] = m;
    __syncthreads();
    if (t < 8) {
        float w = red[t];
        #pragma unroll
        for (int off = 4; off; off >>= 1) w = fmaxf(w, __shfl_xor_sync(0xffu, w, off));
        red[t] = w;
    }
    __syncthreads();
    m = red[0];
    __syncthreads();
    float s = 0.f;
    #pragma unroll
    for (int j = 0; j < 4; j++) { v[j] = expf(v[j] - m); s += v[j]; }
    #pragma unroll
    for (int off = 16; off; off >>= 1) s += __shfl_xor_sync(0xffffffffu, s, off);
    if (lane == 0) red[wrp] = s;
    __syncthreads();
    if (t < 8) {
        float w = red[t];
        #pragma unroll
        for (int off = 4; off; off >>= 1) w += __shfl_xor_sync(0xffu, w, off);
        red[t] = w;
    }
    __syncthreads();
    const float inv = 1.f / red[0];
    #pragma unroll
    for (int j = 0; j < 4; j++) s_attn[t * 4 + j] = v[j] * inv;
    __syncthreads();

    const int o   = blockIdx.x * 32 + (t & 31);
    const int seg = t >> 5;
    const int c0  = seg * 128;
    float acc = 0.f;
    #pragma unroll 4
    for (int c = 0; c < 128; c++)
        acc = fmaf(s_attn[c0 + c], vals[(size_t)(c0 + c) * DOUT + o], acc);
    s_part[seg][t & 31] = acc;
    __syncthreads();
    if (t < 32) {
        float tot = 0.f;
        #pragma unroll
        for (int g = 0; g < 8; g++) tot += s_part[g][t];
        g_mem_out[blockIdx.x * 32 + t] = tot;
    }
}

// ---------------------------------------------------------------- permuting converters
// One warp converts one 16x16 tile (512B out). Lane l (g=l>>2, t=l&3) writes 16B.
// A-order regs: [(g,2t), (8+g,2t), (g,8+2t), (8+g,8+2t)]  (each = 2 consecutive cols)
// B-order regs: [(g,2t), (g,8+2t), (8+g,2t), (8+g,8+2t)]
__device__ __forceinline__ uint32_t pack_h2(float2 p) {
    __half2 h = __floats2half2_rn(p.x, p.y);
    return *reinterpret_cast<uint32_t*>(&h);
}

__global__ void convert_perm_kernel(const float* __restrict__ x,
                                    const float* __restrict__ w) {
    // blocks [0, NM16*NK16/8): x tiles (A-order); rest: w tiles (B-order)
    const int warp_g = blockIdx.x * 8 + (threadIdx.x >> 5);
    const int lane = threadIdx.x & 31;
    const int g = lane >> 2, t = lane & 3;
    const int XW = NM16 * NK16 / 8;   // 16384 blocks worth of x warps

    const float* src;
    __half* dst;
    int tile;
    bool is_a;
    if (blockIdx.x < XW) {
        tile = warp_g; src = x; dst = g_xp; is_a = true;
    } else {
        tile = warp_g - XW * 8; src = w; dst = g_wp; is_a = false;
    }
    const int r16 = tile >> 8;        // m16 or n16  (NK16 = 256)
    const int k16 = tile & 255;
    const float* s = src + (size_t)(r16 * 16) * DIN + k16 * 16;

    float2 p0 = *reinterpret_cast<const float2*>(s + (size_t)g * DIN + 2 * t);
    float2 p1 = *reinterpret_cast<const float2*>(s + (size_t)(g + 8) * DIN + 2 * t);
    float2 p2 = *reinterpret_cast<const float2*>(s + (size_t)g * DIN + 8 + 2 * t);
    float2 p3 = *reinterpret_cast<const float2*>(s + (size_t)(g + 8) * DIN + 8 + 2 * t);

    uint4 out;
    if (is_a) { out.x = pack_h2(p0); out.y = pack_h2(p1); out.z = pack_h2(p2); out.w = pack_h2(p3); }
    else      { out.x = pack_h2(p0); out.y = pack_h2(p2); out.z = pack_h2(p1); out.w = pack_h2(p3); }
    reinterpret_cast<uint4*>(dst)[(size_t)tile * 32 + lane] = out;
}

// ---------------------------------------------------------------- main GEMM
// C[m,n] = scale[n] * (x[m,:].w[n,:]) + 0.01*mem_out[n]
// Pure LDG.128 + HMMA streaming: no smem staging, no barriers in mainloop.
__global__ __launch_bounds__(NTHREADS, 2)
void gemm_mma_kernel(const float* __restrict__ scales, float* __restrict__ C) {
    __shared__ float s_scale[BN];
    __shared__ float s_memo[BN];

    const int tid  = threadIdx.x;
    const int wid  = tid >> 5;
    const int lane = tid & 31;
    const int warp_m = wid & 1;        // 2 strips of 64 rows
    const int warp_n = wid >> 1;       // 4 strips of 32 cols
    const int block_m = blockIdx.x * BM;   // m fast -> co-resident CTAs share W in L1/L2
    const int block_n = blockIdx.y * BN;

    for (int i = tid; i < BN; i += NTHREADS) {
        s_scale[i] = scales[block_n + i];
        s_memo[i]  = 0.01f * g_mem_out[block_n + i];
    }
    __syncthreads();

    const int m16_0 = (block_m + warp_m * 64) >> 4;
    const int n16_0 = (block_n + warp_n * 32) >> 4;
    const uint4* pA = reinterpret_cast<const uint4*>(g_xp) + (size_t)m16_0 * NK16 * 32 + lane;
    const uint4* pB = reinterpret_cast<const uint4*>(g_wp) + (size_t)n16_0 * NK16 * 32 + lane;
    // frag strides (uint4 units): next 16-row strip = NK16*32 = 8192; next k16 = 32
    #define A_FSTRIDE 8192
    #define K_STRIDE  32

    float acc[4][4][4];
    #pragma unroll
    for (int i = 0; i < 4; i++)
        #pragma unroll
        for (int t = 0; t < 4; t++)
            #pragma unroll
            for (int r = 0; r < 4; r++) acc[i][t][r] = 0.f;

    uint4 afA[4], bfA[2], afB[4], bfB[2];

    auto ldA = [&](int k16, uint4 af[4]) {
        const uint4* p = pA + k16 * K_STRIDE;
        #pragma unroll
        for (int i = 0; i < 4; i++) af[i] = p[i * A_FSTRIDE];
    };
    auto ldB = [&](int k16, uint4 bf[2]) {
        const uint4* p = pB + k16 * K_STRIDE;
        #pragma unroll
        for (int q = 0; q < 2; q++) bf[q] = p[q * A_FSTRIDE];
    };
    auto do_mma = [&](uint4 af[4], uint4 bf[2]) {
        #pragma unroll
        for (int p = 0; p < 2; p++) {
            const uint32_t* bp = reinterpret_cast<const uint32_t*>(&bf[p]);
            #pragma unroll
            for (int i = 0; i < 4; i++) {
                const uint32_t* ap = reinterpret_cast<const uint32_t*>(&af[i]);
                mma16816(acc[i][2 * p],     ap, bp);
                mma16816(acc[i][2 * p + 1], ap, bp + 2);
            }
        }
    };

    ldA(0, afA); ldB(0, bfA);
    for (int k = 0; k < NK16; k += 2) {
        ldA(k + 1, afB); ldB(k + 1, bfB);
        do_mma(afA, bfA);
        if (k + 2 < NK16) { ldA(k + 2, afA); ldB(k + 2, bfA); }
        do_mma(afB, bfB);
    }

    // ---------------- epilogue ----------------
    const int groupID = lane >> 2;
    const int tidg    = lane & 3;
    #pragma unroll
    for (int i = 0; i < 4; i++) {
        const int m0 = block_m + warp_m * 64 + i * 16 + groupID;
        #pragma unroll
        for (int t = 0; t < 4; t++) {
            const int ln = warp_n * 32 + t * 8 + tidg * 2;
            const float sc0 = s_scale[ln],     mo0 = s_memo[ln];
            const float sc1 = s_scale[ln + 1], mo1 = s_memo[ln + 1];
            float2 o0, o1;
            o0.x = fmaf(acc[i][t][0], sc0, mo0);
            o0.y = fmaf(acc[i][t][1], sc1, mo1);
            o1.x = fmaf(acc[i][t][2], sc0, mo0);
            o1.y = fmaf(acc[i][t][3], sc1, mo1);
            *reinterpret_cast<float2*>(C + (size_t)m0 * DOUT + block_n + ln)       = o0;
            *reinterpret_cast<float2*>(C + (size_t)(m0 + 8) * DOUT + block_n + ln) = o1;
        }
    }
}

// ---------------------------------------------------------------- host launch
extern "C" void kernel_launch(void* const* d_in, const int* in_sizes, int n_in,
                              void* d_out, int out_size) {
    const float* x      = (const float*)d_in[0];  // [B,S,DIN]
    const float* wlat   = (const float*)d_in[1];  // [DOUT,DIN]
    const float* wscale = (const float*)d_in[2];  // [DOUT,1]
    const float* mkeys  = (const float*)d_in[3];  // [CAP,DIN]
    const float* mvals  = (const float*)d_in[4];  // [CAP,DOUT]
    float* out = (float*)d_out;                   // [B,S,DOUT]
    (void)in_sizes; (void)n_in; (void)out_size;

    // permuting conversion: x tiles then w tiles, one launch
    {
        int xblocks = NM16 * NK16 / 8;     // 16384
        int wblocks = NN16 * NK16 / 8;     // 8192
        convert_perm_kernel<<<xblocks + wblocks, 256>>>(x, wlat);
    }

    // associative memory path
    scores_kernel<<<CAP, 256>>>(mkeys, x);
    memout_fused_kernel<<<DOUT / 32, 256>>>(mvals);

    // main GEMM (no dynamic smem)
    dim3 grid(MTOT / BM, DOUT / BN);   // 64 x 32 (m fast)
    gemm_mma_kernel<<<grid, NTHREADS>>>(wscale, out);
}